// round 9
// baseline (speedup 1.0000x reference)
#include <cuda_runtime.h>
#include <cuda_bf16.h>

// Problem constants
#define C_IN  64
#define C_OUT 64
#define XD 32
#define XH 64
#define XW 64
#define OD 64
#define OH 128
#define OW 128
#define ZD 68
#define ZH 132
#define ZW 132

#define X_CH_STRIDE (XD*XH*XW)      // 131072
#define O_CH_STRIDE (OD*OH*OW)      // 1048576

#define NUM_SMS 148
#define CTAS_PER_SM 6
#define GRID (NUM_SMS * CTAS_PER_SM)          // 888, exactly one wave
#define CONV_CTAS (GRID / 3)                  // 296 (bid % 3 == 0)
#define COPY_CTAS (GRID - CONV_CTAS)          // 592

#define NUM_CONV_TILES 4096                   // 32 d' * 64 h' * 2 halves
#define NUM_COPY_CHUNKS 4096                  // 128 rows each

__global__ __launch_bounds__(256, 6)
void upconv_cropcat_kernel(const float* __restrict__ x,
                           const float* __restrict__ z,
                           const float* __restrict__ W,
                           const float* __restrict__ b,
                           float* __restrict__ out)
{
    __shared__ float xs[64 * 32];     // [c][w'] half-plane tile, 8 KB
    __shared__ float Ws[64 * 65];     // [o][c] padded (conflict-free), 16.25 KB
    __shared__ float bs[64];

    const int bid = blockIdx.x;
    const int tid = threadIdx.x;

    if (bid % 3 == 0) {
        // =============== conv pool: 296 persistent CTAs ===============
        const int pool_id = bid / 3;

        // Stage W (4096 floats) ONCE per CTA into padded rows.
        const float4* __restrict__ W4 = (const float4*)W;
        #pragma unroll
        for (int i = tid; i < 1024; i += 256) {
            float4 v = W4[i];
            int o  = i >> 4;
            int c4 = (i & 15) << 2;
            float* dst = &Ws[o * 65 + c4];
            dst[0] = v.x; dst[1] = v.y; dst[2] = v.z; dst[3] = v.w;
        }
        if (tid < 64) bs[tid] = b[tid];

        const int wo = tid & 7;    // w-quad within half-plane
        const int oo = tid >> 3;   // o-pair: o = oo*2, oo*2+1
        const float4* __restrict__ xcol = (const float4*)xs + wo;

        for (int t = pool_id; t < NUM_CONV_TILES; t += CONV_CTAS) {
            const int dp   = t >> 7;        // 0..31
            const int hp   = (t >> 1) & 63; // 0..63
            const int half = t & 1;         // w' offset 0 or 32

            __syncthreads();   // prior tile's xs reads complete (and W ready)

            // Stage x tile: 64 channels x 32 w' (contiguous per channel).
            const float* __restrict__ xbase =
                x + dp * (XH * XW) + hp * XW + half * 32;
            float4* xs4 = (float4*)xs;
            #pragma unroll
            for (int i = tid; i < 512; i += 256) {
                int c  = i >> 3;
                int w4 = i & 7;
                xs4[i] = *(const float4*)(xbase + (size_t)c * X_CH_STRIDE + w4 * 4);
            }
            __syncthreads();

            float acc[2][4];
            #pragma unroll
            for (int j = 0; j < 2; j++)
                #pragma unroll
                for (int k = 0; k < 4; k++)
                    acc[j][k] = 0.0f;

            #pragma unroll 8
            for (int c = 0; c < 64; c++) {
                float4 xv = xcol[c * 8];
                #pragma unroll
                for (int j = 0; j < 2; j++) {
                    float wv = Ws[(oo * 2 + j) * 65 + c];
                    acc[j][0] = fmaf(wv, xv.x, acc[j][0]);
                    acc[j][1] = fmaf(wv, xv.y, acc[j][1]);
                    acc[j][2] = fmaf(wv, xv.z, acc[j][2]);
                    acc[j][3] = fmaf(wv, xv.w, acc[j][3]);
                }
            }

            // Epilogue: duplicate 2x along w, write 4 output rows (2d x 2h).
            #pragma unroll
            for (int j = 0; j < 2; j++) {
                const int o = oo * 2 + j;
                const float bb = bs[o];
                float4 lo = make_float4(acc[j][0] + bb, acc[j][0] + bb,
                                        acc[j][1] + bb, acc[j][1] + bb);
                float4 hi = make_float4(acc[j][2] + bb, acc[j][2] + bb,
                                        acc[j][3] + bb, acc[j][3] + bb);
                float* obase = out + (size_t)o * O_CH_STRIDE
                                   + (size_t)(2 * dp) * (OH * OW)
                                   + (2 * hp) * OW + half * 64 + wo * 8;
                #pragma unroll
                for (int dd = 0; dd < 2; dd++) {
                    #pragma unroll
                    for (int hh = 0; hh < 2; hh++) {
                        float* p = obase + dd * (OH * OW) + hh * OW;
                        __stcs((float4*)p,     lo);
                        __stcs((float4*)(p+4), hi);
                    }
                }
            }
        }
    } else {
        // =============== copy pool: 592 persistent CTAs ===============
        // out[64+c, d, h, 0:128] = z[c, d+2, h+2, 2:130]
        const int pool_id = bid - bid / 3 - 1;   // 0..591
        const int warp = tid >> 5;
        const int lane = tid & 31;

        for (int chunk = pool_id; chunk < NUM_COPY_CHUNKS; chunk += COPY_CTAS) {
            // Each warp: 16 h-consecutive rows within one (c, d) plane.
            const int r0 = chunk * 128 + warp * 16;

            const int c   = r0 >> 13;        // / (64*128)
            const int rem = r0 & 8191;
            const int d   = rem >> 7;
            const int h0  = rem & 127;

            const float* src =
                z + ((size_t)((c * ZD + d + 2) * ZH + (h0 + 2))) * ZW
                  + 2 + lane * 4;
            float* dst = out + (size_t)(64 + c) * O_CH_STRIDE
                             + (size_t)d * (OH * OW) + h0 * OW + lane * 4;

            // Batch 8 rows of loads (16 LDG.64 in flight) before stores.
            #pragma unroll
            for (int jj = 0; jj < 16; jj += 8) {
                float2 a[8], bb2[8];
                #pragma unroll
                for (int i = 0; i < 8; i++) {
                    const float* s = src + (jj + i) * ZW;
                    a[i]   = __ldcs((const float2*)s);
                    bb2[i] = __ldcs((const float2*)(s + 2));
                }
                #pragma unroll
                for (int i = 0; i < 8; i++) {
                    __stcs((float4*)(dst + (jj + i) * OW),
                           make_float4(a[i].x, a[i].y, bb2[i].x, bb2[i].y));
                }
            }
        }
    }
}

extern "C" void kernel_launch(void* const* d_in, const int* in_sizes, int n_in,
                              void* d_out, int out_size)
{
    const float* x = (const float*)d_in[0];   // (1,64,32,64,64)
    const float* z = (const float*)d_in[1];   // (1,64,68,132,132)
    const float* W = (const float*)d_in[2];   // (64,64)
    const float* b = (const float*)d_in[3];   // (64,)
    float* out = (float*)d_out;               // (1,128,64,128,128)

    upconv_cropcat_kernel<<<GRID, 256>>>(x, z, W, b, out);
}

// round 10
// speedup vs baseline: 1.1507x; 1.1507x over previous
#include <cuda_runtime.h>
#include <cuda_bf16.h>

// Problem constants
#define C_IN  64
#define C_OUT 64
#define XD 32
#define XH 64
#define XW 64
#define OD 64
#define OH 128
#define OW 128
#define ZD 68
#define ZH 132
#define ZW 132

#define X_CH_STRIDE (XD*XH*XW)      // 131072
#define O_CH_STRIDE (OD*OH*OW)      // 1048576

// ---------------------------------------------------------------------------
// Kernel A: upsample-conv. 4096 blocks = 32 d' * 64 h' * 2 half-planes.
// Traffic: 32 MB read (x) + 16 KB (W, L2-resident) + 256 MB write.
// ---------------------------------------------------------------------------
__global__ __launch_bounds__(256)
void upconv_kernel(const float* __restrict__ x,
                   const float* __restrict__ W,
                   const float* __restrict__ b,
                   float* __restrict__ out)
{
    __shared__ float xs[64 * 32];     // [c][w'] half-plane tile, 8 KB
    __shared__ float Ws[64 * 65];     // [o][c] padded (conflict-free), 16.25 KB
    __shared__ float bs[64];

    const int bid = blockIdx.x;
    const int tid = threadIdx.x;

    const int dp   = bid >> 7;        // 0..31
    const int hp   = (bid >> 1) & 63; // 0..63
    const int half = bid & 1;         // w' offset 0 or 32

    // Stage W (4096 floats) via float4 loads into padded rows.
    const float4* __restrict__ W4 = (const float4*)W;
    #pragma unroll
    for (int i = tid; i < 1024; i += 256) {
        float4 v = W4[i];
        int o  = i >> 4;
        int c4 = (i & 15) << 2;
        float* dst = &Ws[o * 65 + c4];
        dst[0] = v.x; dst[1] = v.y; dst[2] = v.z; dst[3] = v.w;
    }

    // Stage x tile: 64 channels x 32 w' (contiguous per channel).
    const float* __restrict__ xbase =
        x + dp * (XH * XW) + hp * XW + half * 32;
    float4* xs4 = (float4*)xs;
    #pragma unroll
    for (int i = tid; i < 512; i += 256) {
        int c  = i >> 3;
        int w4 = i & 7;
        xs4[i] = *(const float4*)(xbase + (size_t)c * X_CH_STRIDE + w4 * 4);
    }
    if (tid < 64) bs[tid] = b[tid];
    __syncthreads();

    // Each thread: 2 output channels x 4 small-w values.
    const int wo = tid & 7;    // w-quad: w' = half*32 + wo*4 .. +3
    const int oo = tid >> 3;   // o-pair: o = oo*2, oo*2+1

    float acc[2][4];
    #pragma unroll
    for (int j = 0; j < 2; j++)
        #pragma unroll
        for (int k = 0; k < 4; k++)
            acc[j][k] = 0.0f;

    const float4* __restrict__ xcol = (const float4*)xs + wo;
    #pragma unroll 8
    for (int c = 0; c < 64; c++) {
        float4 xv = xcol[c * 8];
        #pragma unroll
        for (int j = 0; j < 2; j++) {
            float wv = Ws[(oo * 2 + j) * 65 + c];
            acc[j][0] = fmaf(wv, xv.x, acc[j][0]);
            acc[j][1] = fmaf(wv, xv.y, acc[j][1]);
            acc[j][2] = fmaf(wv, xv.z, acc[j][2]);
            acc[j][3] = fmaf(wv, xv.w, acc[j][3]);
        }
    }

    // Epilogue: duplicate each value 2x along w, write 4 output rows (2d x 2h).
    #pragma unroll
    for (int j = 0; j < 2; j++) {
        const int o = oo * 2 + j;
        const float bb = bs[o];
        float4 lo = make_float4(acc[j][0] + bb, acc[j][0] + bb,
                                acc[j][1] + bb, acc[j][1] + bb);
        float4 hi = make_float4(acc[j][2] + bb, acc[j][2] + bb,
                                acc[j][3] + bb, acc[j][3] + bb);
        float* obase = out + (size_t)o * O_CH_STRIDE
                           + (size_t)(2 * dp) * (OH * OW)
                           + (2 * hp) * OW + half * 64 + wo * 8;
        #pragma unroll
        for (int dd = 0; dd < 2; dd++) {
            #pragma unroll
            for (int hh = 0; hh < 2; hh++) {
                float* p = obase + dd * (OH * OW) + hh * OW;
                __stcs((float4*)p,     lo);
                __stcs((float4*)(p+4), hi);
            }
        }
    }
}

// ---------------------------------------------------------------------------
// Kernel B: crop-copy. out[64+c, d, h, 0:128] = z[c, d+2, h+2, 2:130]
// 4096 blocks, each warp copies 16 h-consecutive rows in one (c,d) plane,
// batching 8 rows of loads (16 LDG.64 in flight) before storing.
// Traffic: 256 MB read + 256 MB write.
// ---------------------------------------------------------------------------
__global__ __launch_bounds__(256)
void cropcopy_kernel(const float* __restrict__ z,
                     float* __restrict__ out)
{
    const int bid  = blockIdx.x;
    const int tid  = threadIdx.x;
    const int warp = tid >> 5;
    const int lane = tid & 31;

    const int r0 = (bid * 8 + warp) * 16;   // 32768 warps * 16 = 524288 rows

    const int c   = r0 >> 13;        // / (64*128)
    const int rem = r0 & 8191;
    const int d   = rem >> 7;
    const int h0  = rem & 127;

    const float* src =
        z + ((size_t)((c * ZD + d + 2) * ZH + (h0 + 2))) * ZW + 2 + lane * 4;
    float* dst = out + (size_t)(64 + c) * O_CH_STRIDE
                     + (size_t)d * (OH * OW) + h0 * OW + lane * 4;

    #pragma unroll
    for (int jj = 0; jj < 16; jj += 8) {
        float2 a[8], bb2[8];
        #pragma unroll
        for (int i = 0; i < 8; i++) {
            const float* s = src + (jj + i) * ZW;
            a[i]   = __ldcs((const float2*)s);
            bb2[i] = __ldcs((const float2*)(s + 2));
        }
        #pragma unroll
        for (int i = 0; i < 8; i++) {
            __stcs((float4*)(dst + (jj + i) * OW),
                   make_float4(a[i].x, a[i].y, bb2[i].x, bb2[i].y));
        }
    }
}

extern "C" void kernel_launch(void* const* d_in, const int* in_sizes, int n_in,
                              void* d_out, int out_size)
{
    const float* x = (const float*)d_in[0];   // (1,64,32,64,64)
    const float* z = (const float*)d_in[1];   // (1,64,68,132,132)
    const float* W = (const float*)d_in[2];   // (64,64)
    const float* b = (const float*)d_in[3];   // (64,)
    float* out = (float*)d_out;               // (1,128,64,128,128)

    upconv_kernel<<<4096, 256>>>(x, W, b, out);
    cropcopy_kernel<<<4096, 256>>>(z, out);
}

// round 11
// speedup vs baseline: 1.1523x; 1.0014x over previous
#include <cuda_runtime.h>
#include <cuda_bf16.h>

// Problem constants
#define C_IN  64
#define C_OUT 64
#define XD 32
#define XH 64
#define XW 64
#define OD 64
#define OH 128
#define OW 128
#define ZD 68
#define ZH 132
#define ZW 132

#define X_CH_STRIDE (XD*XH*XW)      // 131072
#define O_CH_STRIDE (OD*OH*OW)      // 1048576

// ---------------------------------------------------------------------------
// Kernel A: upsample-conv. 4096 blocks = 32 d' * 64 h' * 2 half-planes.
// Traffic: 32 MB read (x) + 16 KB (W, L2-resident) + 256 MB write.
// ---------------------------------------------------------------------------
__global__ __launch_bounds__(256)
void upconv_kernel(const float* __restrict__ x,
                   const float* __restrict__ W,
                   const float* __restrict__ b,
                   float* __restrict__ out)
{
    __shared__ float xs[64 * 32];     // [c][w'] half-plane tile, 8 KB
    __shared__ float Ws[64 * 65];     // [o][c] padded (conflict-free), 16.25 KB
    __shared__ float bs[64];

    const int bid = blockIdx.x;
    const int tid = threadIdx.x;

    const int dp   = bid >> 7;        // 0..31
    const int hp   = (bid >> 1) & 63; // 0..63
    const int half = bid & 1;         // w' offset 0 or 32

    // Stage W (4096 floats) via float4 loads into padded rows.
    const float4* __restrict__ W4 = (const float4*)W;
    #pragma unroll
    for (int i = tid; i < 1024; i += 256) {
        float4 v = W4[i];
        int o  = i >> 4;
        int c4 = (i & 15) << 2;
        float* dst = &Ws[o * 65 + c4];
        dst[0] = v.x; dst[1] = v.y; dst[2] = v.z; dst[3] = v.w;
    }

    // Stage x tile: 64 channels x 32 w' (contiguous per channel).
    const float* __restrict__ xbase =
        x + dp * (XH * XW) + hp * XW + half * 32;
    float4* xs4 = (float4*)xs;
    #pragma unroll
    for (int i = tid; i < 512; i += 256) {
        int c  = i >> 3;
        int w4 = i & 7;
        xs4[i] = *(const float4*)(xbase + (size_t)c * X_CH_STRIDE + w4 * 4);
    }
    if (tid < 64) bs[tid] = b[tid];
    __syncthreads();

    // Each thread: 2 output channels x 4 small-w values.
    const int wo = tid & 7;    // w-quad: w' = half*32 + wo*4 .. +3
    const int oo = tid >> 3;   // o-pair: o = oo*2, oo*2+1

    float acc[2][4];
    #pragma unroll
    for (int j = 0; j < 2; j++)
        #pragma unroll
        for (int k = 0; k < 4; k++)
            acc[j][k] = 0.0f;

    const float4* __restrict__ xcol = (const float4*)xs + wo;
    #pragma unroll 8
    for (int c = 0; c < 64; c++) {
        float4 xv = xcol[c * 8];
        #pragma unroll
        for (int j = 0; j < 2; j++) {
            float wv = Ws[(oo * 2 + j) * 65 + c];
            acc[j][0] = fmaf(wv, xv.x, acc[j][0]);
            acc[j][1] = fmaf(wv, xv.y, acc[j][1]);
            acc[j][2] = fmaf(wv, xv.z, acc[j][2]);
            acc[j][3] = fmaf(wv, xv.w, acc[j][3]);
        }
    }

    // Epilogue: duplicate each value 2x along w, write 4 output rows (2d x 2h).
    #pragma unroll
    for (int j = 0; j < 2; j++) {
        const int o = oo * 2 + j;
        const float bb = bs[o];
        float4 lo = make_float4(acc[j][0] + bb, acc[j][0] + bb,
                                acc[j][1] + bb, acc[j][1] + bb);
        float4 hi = make_float4(acc[j][2] + bb, acc[j][2] + bb,
                                acc[j][3] + bb, acc[j][3] + bb);
        float* obase = out + (size_t)o * O_CH_STRIDE
                           + (size_t)(2 * dp) * (OH * OW)
                           + (2 * hp) * OW + half * 64 + wo * 8;
        #pragma unroll
        for (int dd = 0; dd < 2; dd++) {
            #pragma unroll
            for (int hh = 0; hh < 2; hh++) {
                float* p = obase + dd * (OH * OW) + hh * OW;
                __stcs((float4*)p,     lo);
                __stcs((float4*)(p+4), hi);
            }
        }
    }
}

// ---------------------------------------------------------------------------
// Kernel B: crop-copy. out[64+c, d, h, 0:128] = z[c, d+2, h+2, 2:130]
// 4096 blocks, each warp copies 16 h-consecutive rows in one (c,d) plane,
// batching 8 rows of loads (16 LDG.64 in flight) before storing.
// Traffic: 256 MB read + 256 MB write.
// ---------------------------------------------------------------------------
__global__ __launch_bounds__(256)
void cropcopy_kernel(const float* __restrict__ z,
                     float* __restrict__ out)
{
    const int bid  = blockIdx.x;
    const int tid  = threadIdx.x;
    const int warp = tid >> 5;
    const int lane = tid & 31;

    const int r0 = (bid * 8 + warp) * 16;   // 32768 warps * 16 = 524288 rows

    const int c   = r0 >> 13;        // / (64*128)
    const int rem = r0 & 8191;
    const int d   = rem >> 7;
    const int h0  = rem & 127;

    const float* src =
        z + ((size_t)((c * ZD + d + 2) * ZH + (h0 + 2))) * ZW + 2 + lane * 4;
    float* dst = out + (size_t)(64 + c) * O_CH_STRIDE
                     + (size_t)d * (OH * OW) + h0 * OW + lane * 4;

    #pragma unroll
    for (int jj = 0; jj < 16; jj += 8) {
        float2 a[8], bb2[8];
        #pragma unroll
        for (int i = 0; i < 8; i++) {
            const float* s = src + (jj + i) * ZW;
            a[i]   = __ldcs((const float2*)s);
            bb2[i] = __ldcs((const float2*)(s + 2));
        }
        #pragma unroll
        for (int i = 0; i < 8; i++) {
            __stcs((float4*)(dst + (jj + i) * OW),
                   make_float4(a[i].x, a[i].y, bb2[i].x, bb2[i].y));
        }
    }
}

extern "C" void kernel_launch(void* const* d_in, const int* in_sizes, int n_in,
                              void* d_out, int out_size)
{
    const float* x = (const float*)d_in[0];   // (1,64,32,64,64)
    const float* z = (const float*)d_in[1];   // (1,64,68,132,132)
    const float* W = (const float*)d_in[2];   // (64,64)
    const float* b = (const float*)d_in[3];   // (64,)
    float* out = (float*)d_out;               // (1,128,64,128,128)

    upconv_kernel<<<4096, 256>>>(x, W, b, out);
    cropcopy_kernel<<<4096, 256>>>(z, out);
}

// round 14
// speedup vs baseline: 1.4165x; 1.2293x over previous
#include <cuda_runtime.h>
#include <cuda_bf16.h>

// Problem constants
#define C_IN  64
#define C_OUT 64
#define XD 32
#define XH 64
#define XW 64
#define OD 64
#define OH 128
#define OW 128
#define ZD 68
#define ZH 132
#define ZW 132

#define X_CH_STRIDE (XD*XH*XW)      // 131072
#define O_CH_STRIDE (OD*OH*OW)      // 1048576

#define NUM_CONV_BLOCKS 4096        // 32 d' * 64 h' * 2 half-planes
#define NUM_COPY_BLOCKS 4096
#define NUM_BLOCKS (NUM_CONV_BLOCKS + NUM_COPY_BLOCKS)

// Wt row pitch in floats. MUST be >= 64 (o index range!) -- the R12/R13 bug
// was pitch=34, which made transposed rows overlap and scrambled W.
// 66 = even (8B-aligned float2 reads) and 66 mod 32 = 2 (conflict-free).
#define WT_PITCH 66

__global__ __launch_bounds__(256)
void upconv_cropcat_kernel(const float* __restrict__ x,
                           const float* __restrict__ z,
                           const float* __restrict__ W,
                           const float* __restrict__ b,
                           float* __restrict__ out)
{
    __shared__ __align__(16) float xs[64 * 32];        // [c][w'] tile, 8 KB
    __shared__ __align__(16) float Wt[64 * WT_PITCH];  // [c][o] transposed, 16.5 KB
    __shared__ float bs[64];

    const int bid = blockIdx.x;
    const int tid = threadIdx.x;

    if ((bid & 1) == 0) {
        // ------------------- conv part: half of one (d', h') plane -----------
        const int aid  = bid >> 1;        // 0..4095
        const int dp   = aid >> 7;        // 0..31
        const int hp   = (aid >> 1) & 63; // 0..63
        const int half = aid & 1;         // w' offset 0 or 32

        // Stage W transposed: Wt[c][o] = W[o][c].
        const float4* __restrict__ W4 = (const float4*)W;
        #pragma unroll
        for (int i = tid; i < 1024; i += 256) {
            float4 v = W4[i];
            int o  = i >> 4;            // 0..63
            int c4 = (i & 15) << 2;     // 0..60
            Wt[(c4 + 0) * WT_PITCH + o] = v.x;
            Wt[(c4 + 1) * WT_PITCH + o] = v.y;
            Wt[(c4 + 2) * WT_PITCH + o] = v.z;
            Wt[(c4 + 3) * WT_PITCH + o] = v.w;
        }

        // Stage x tile: 64 channels x 32 w' (contiguous per channel).
        const float* __restrict__ xbase =
            x + dp * (XH * XW) + hp * XW + half * 32;
        float4* xs4 = (float4*)xs;
        #pragma unroll
        for (int i = tid; i < 512; i += 256) {
            int c  = i >> 3;
            int w4 = i & 7;
            xs4[i] = *(const float4*)(xbase + (size_t)c * X_CH_STRIDE + w4 * 4);
        }
        if (tid < 64) bs[tid] = b[tid];
        __syncthreads();

        // Each thread: 2 output channels x 4 small-w values, packed f32x2.
        const int wo = tid & 7;    // w-quad: w' = half*32 + wo*4 .. +3
        const int oo = tid >> 3;   // o-pair: o = oo*2, oo*2+1

        const unsigned xs_addr =
            (unsigned)__cvta_generic_to_shared(xs) + wo * 16;

        unsigned long long acc00 = 0ull, acc01 = 0ull;  // o0: {w0,w1},{w2,w3}
        unsigned long long acc10 = 0ull, acc11 = 0ull;  // o1

        #pragma unroll 8
        for (int c = 0; c < 64; c++) {
            float2 wv = *(const float2*)&Wt[c * WT_PITCH + oo * 2];
            unsigned w0u = __float_as_uint(wv.x);
            unsigned w1u = __float_as_uint(wv.y);
            // Vector LDS + packs + 4 packed FMAs in one block.
            asm volatile(
                "{\n\t"
                ".reg .b64 xa, xb, wda, wdb;\n\t"
                "ld.shared.v2.b64 {xa, xb}, [%4];\n\t"
                "mov.b64 wda, {%5, %5};\n\t"
                "mov.b64 wdb, {%6, %6};\n\t"
                "fma.rn.f32x2 %0, wda, xa, %0;\n\t"
                "fma.rn.f32x2 %1, wda, xb, %1;\n\t"
                "fma.rn.f32x2 %2, wdb, xa, %2;\n\t"
                "fma.rn.f32x2 %3, wdb, xb, %3;\n\t"
                "}"
                : "+l"(acc00), "+l"(acc01), "+l"(acc10), "+l"(acc11)
                : "r"(xs_addr + c * 128), "r"(w0u), "r"(w1u));
        }

        // Epilogue: unpack, add bias, duplicate 2x along w, write 4 rows each.
        #pragma unroll
        for (int j = 0; j < 2; j++) {
            const int o = oo * 2 + j;
            const float bb = bs[o];
            unsigned u0, u1, u2, u3;
            if (j == 0) {
                asm("mov.b64 {%0, %1}, %2;" : "=r"(u0), "=r"(u1) : "l"(acc00));
                asm("mov.b64 {%0, %1}, %2;" : "=r"(u2), "=r"(u3) : "l"(acc01));
            } else {
                asm("mov.b64 {%0, %1}, %2;" : "=r"(u0), "=r"(u1) : "l"(acc10));
                asm("mov.b64 {%0, %1}, %2;" : "=r"(u2), "=r"(u3) : "l"(acc11));
            }
            float v0 = __uint_as_float(u0) + bb;
            float v1 = __uint_as_float(u1) + bb;
            float v2 = __uint_as_float(u2) + bb;
            float v3 = __uint_as_float(u3) + bb;
            float4 lo = make_float4(v0, v0, v1, v1);
            float4 hi = make_float4(v2, v2, v3, v3);
            float* obase = out + (size_t)o * O_CH_STRIDE
                               + (size_t)(2 * dp) * (OH * OW)
                               + (2 * hp) * OW + half * 64 + wo * 8;
            #pragma unroll
            for (int dd = 0; dd < 2; dd++) {
                #pragma unroll
                for (int hh = 0; hh < 2; hh++) {
                    float* p = obase + dd * (OH * OW) + hh * OW;
                    __stcs((float4*)p,     lo);
                    __stcs((float4*)(p+4), hi);
                }
            }
        }
    } else {
        // ------------------- crop-copy part (R8 body, unchanged) -------------
        // out[64+c, d, h, 0:128] = z[c, d+2, h+2, 2:130]
        const int cid  = bid >> 1;
        const int warp = tid >> 5;
        const int lane = tid & 31;
        const int r0 = (cid * 8 + warp) * 16;   // 32768 warps * 16 = 524288 rows

        const int c   = r0 >> 13;        // / (64*128)
        const int rem = r0 & 8191;
        const int d   = rem >> 7;
        const int h0  = rem & 127;

        const float* src =
            z + ((size_t)((c * ZD + d + 2) * ZH + (h0 + 2))) * ZW + 2 + lane * 4;
        float* dst = out + (size_t)(64 + c) * O_CH_STRIDE
                         + (size_t)d * (OH * OW) + h0 * OW + lane * 4;

        #pragma unroll
        for (int jj = 0; jj < 16; jj += 8) {
            float2 a[8], bb2[8];
            #pragma unroll
            for (int i = 0; i < 8; i++) {
                const float* s = src + (jj + i) * ZW;
                a[i]   = __ldcs((const float2*)s);
                bb2[i] = __ldcs((const float2*)(s + 2));
            }
            #pragma unroll
            for (int i = 0; i < 8; i++) {
                __stcs((float4*)(dst + (jj + i) * OW),
                       make_float4(a[i].x, a[i].y, bb2[i].x, bb2[i].y));
            }
        }
    }
}

extern "C" void kernel_launch(void* const* d_in, const int* in_sizes, int n_in,
                              void* d_out, int out_size)
{
    const float* x = (const float*)d_in[0];   // (1,64,32,64,64)
    const float* z = (const float*)d_in[1];   // (1,64,68,132,132)
    const float* W = (const float*)d_in[2];   // (64,64)
    const float* b = (const float*)d_in[3];   // (64,)
    float* out = (float*)d_out;               // (1,128,64,128,128)

    upconv_cropcat_kernel<<<NUM_BLOCKS, 256>>>(x, z, W, b, out);
}

// round 15
// speedup vs baseline: 1.4171x; 1.0005x over previous
#include <cuda_runtime.h>
#include <cuda_bf16.h>

// Problem constants
#define C_IN  64
#define C_OUT 64
#define XD 32
#define XH 64
#define XW 64
#define OD 64
#define OH 128
#define OW 128
#define ZD 68
#define ZH 132
#define ZW 132

#define X_CH_STRIDE (XD*XH*XW)      // 131072
#define O_CH_STRIDE (OD*OH*OW)      // 1048576

#define NUM_BLOCKS 4096             // 32 d' * 64 h' * 2 half-planes

// Wt pitch: 68 floats = 17 float4 per c-row; >=64 (R12 lesson), 16B-aligned
// rows, 68 mod 32 = 4 -> the 16B-granule pattern is conflict-free.
#define WT_PITCH 68

__global__ __launch_bounds__(256)
void upconv_cropcat_kernel(const float* __restrict__ x,
                           const float* __restrict__ z,
                           const float* __restrict__ W,
                           const float* __restrict__ b,
                           float* __restrict__ out)
{
    __shared__ __align__(16) float xs[64 * 32];        // [c][w'] tile, 8 KB
    __shared__ __align__(16) float Wt[64 * WT_PITCH];  // [c][o] transposed, 17 KB
    __shared__ float bs[64];

    const int bid  = blockIdx.x;
    const int tid  = threadIdx.x;
    const int warp = tid >> 5;

    if (warp < 4) {
        // =========== conv warps (128 threads): one (d',h') half-plane ========
        const int dp   = bid >> 7;        // 0..31
        const int hp   = (bid >> 1) & 63; // 0..63
        const int half = bid & 1;         // w' offset 0 or 32

        // Stage W transposed: Wt[c][o] = W[o][c]. 1024 float4 over 128 thr.
        const float4* __restrict__ W4 = (const float4*)W;
        #pragma unroll
        for (int i = tid; i < 1024; i += 128) {
            float4 v = W4[i];
            int o  = i >> 4;            // 0..63
            int c4 = (i & 15) << 2;     // 0..60
            Wt[(c4 + 0) * WT_PITCH + o] = v.x;
            Wt[(c4 + 1) * WT_PITCH + o] = v.y;
            Wt[(c4 + 2) * WT_PITCH + o] = v.z;
            Wt[(c4 + 3) * WT_PITCH + o] = v.w;
        }
        // Stage x tile: 64 channels x 32 w'. 512 float4 over 128 thr.
        const float* __restrict__ xbase =
            x + dp * (XH * XW) + hp * XW + half * 32;
        float4* xs4 = (float4*)xs;
        #pragma unroll
        for (int i = tid; i < 512; i += 128) {
            int c  = i >> 3;
            int w4 = i & 7;
            xs4[i] = *(const float4*)(xbase + (size_t)c * X_CH_STRIDE + w4 * 4);
        }
        if (tid < 64) bs[tid] = b[tid];

        // Barrier among the 128 conv threads ONLY -- copy warps never wait.
        asm volatile("bar.sync 1, 128;" ::: "memory");

        // Each thread: 4 output channels x 4 small-w values, packed f32x2.
        const int wo = tid & 7;    // w-quad: w' = half*32 + wo*4 .. +3
        const int oq = tid >> 3;   // 0..15, o = oq*4 .. oq*4+3
        const int o0 = oq << 2;

        const unsigned xs_addr =
            (unsigned)__cvta_generic_to_shared(xs) + wo * 16;
        const float4* __restrict__ Wt4 = (const float4*)Wt;

        unsigned long long acc[4][2];
        #pragma unroll
        for (int j = 0; j < 4; j++) { acc[j][0] = 0ull; acc[j][1] = 0ull; }

        #pragma unroll 4
        for (int c = 0; c < 64; c++) {
            float4 wv = Wt4[c * (WT_PITCH / 4) + oq];
            unsigned w0u = __float_as_uint(wv.x);
            unsigned w1u = __float_as_uint(wv.y);
            unsigned w2u = __float_as_uint(wv.z);
            unsigned w3u = __float_as_uint(wv.w);
            asm volatile(
                "{\n\t"
                ".reg .b64 xa, xb, wd;\n\t"
                "ld.shared.v2.b64 {xa, xb}, [%8];\n\t"
                "mov.b64 wd, {%9, %9};\n\t"
                "fma.rn.f32x2 %0, wd, xa, %0;\n\t"
                "fma.rn.f32x2 %1, wd, xb, %1;\n\t"
                "mov.b64 wd, {%10, %10};\n\t"
                "fma.rn.f32x2 %2, wd, xa, %2;\n\t"
                "fma.rn.f32x2 %3, wd, xb, %3;\n\t"
                "mov.b64 wd, {%11, %11};\n\t"
                "fma.rn.f32x2 %4, wd, xa, %4;\n\t"
                "fma.rn.f32x2 %5, wd, xb, %5;\n\t"
                "mov.b64 wd, {%12, %12};\n\t"
                "fma.rn.f32x2 %6, wd, xa, %6;\n\t"
                "fma.rn.f32x2 %7, wd, xb, %7;\n\t"
                "}"
                : "+l"(acc[0][0]), "+l"(acc[0][1]),
                  "+l"(acc[1][0]), "+l"(acc[1][1]),
                  "+l"(acc[2][0]), "+l"(acc[2][1]),
                  "+l"(acc[3][0]), "+l"(acc[3][1])
                : "r"(xs_addr + c * 128),
                  "r"(w0u), "r"(w1u), "r"(w2u), "r"(w3u));
        }

        // Epilogue: unpack, add bias, duplicate 2x along w, 4 rows per o.
        #pragma unroll
        for (int j = 0; j < 4; j++) {
            const int o = o0 + j;
            const float bb = bs[o];
            unsigned u0, u1, u2, u3;
            asm("mov.b64 {%0, %1}, %2;" : "=r"(u0), "=r"(u1) : "l"(acc[j][0]));
            asm("mov.b64 {%0, %1}, %2;" : "=r"(u2), "=r"(u3) : "l"(acc[j][1]));
            float v0 = __uint_as_float(u0) + bb;
            float v1 = __uint_as_float(u1) + bb;
            float v2 = __uint_as_float(u2) + bb;
            float v3 = __uint_as_float(u3) + bb;
            float4 lo = make_float4(v0, v0, v1, v1);
            float4 hi = make_float4(v2, v2, v3, v3);
            float* obase = out + (size_t)o * O_CH_STRIDE
                               + (size_t)(2 * dp) * (OH * OW)
                               + (2 * hp) * OW + half * 64 + wo * 8;
            #pragma unroll
            for (int dd = 0; dd < 2; dd++) {
                #pragma unroll
                for (int hh = 0; hh < 2; hh++) {
                    float* p = obase + dd * (OH * OW) + hh * OW;
                    __stcs((float4*)p,     lo);
                    __stcs((float4*)(p+4), hi);
                }
            }
        }
    } else {
        // =========== copy warps (128 threads): 128 rows per block ===========
        // out[64+c, d, h, 0:128] = z[c, d+2, h+2, 2:130]
        // Warp cw owns 32 h-consecutive rows in one (c,d) plane
        // (r0 = bid*128 + cw*32 -> h0 = cw*32, stays within the 128-row plane).
        const int cw   = warp - 4;       // 0..3
        const int lane = tid & 31;
        const int r0 = bid * 128 + cw * 32;

        const int c   = r0 >> 13;        // / (64*128)
        const int rem = r0 & 8191;
        const int d   = rem >> 7;
        const int h0  = rem & 127;

        const float* src =
            z + ((size_t)((c * ZD + d + 2) * ZH + (h0 + 2))) * ZW + 2 + lane * 4;
        float* dst = out + (size_t)(64 + c) * O_CH_STRIDE
                         + (size_t)d * (OH * OW) + h0 * OW + lane * 4;

        // 4 batches of 8 rows: 16 LDG.64 in flight before stores (R8 body).
        #pragma unroll
        for (int jj = 0; jj < 32; jj += 8) {
            float2 a[8], bb2[8];
            #pragma unroll
            for (int i = 0; i < 8; i++) {
                const float* s = src + (jj + i) * ZW;
                a[i]   = __ldcs((const float2*)s);
                bb2[i] = __ldcs((const float2*)(s + 2));
            }
            #pragma unroll
            for (int i = 0; i < 8; i++) {
                __stcs((float4*)(dst + (jj + i) * OW),
                       make_float4(a[i].x, a[i].y, bb2[i].x, bb2[i].y));
            }
        }
    }
}

extern "C" void kernel_launch(void* const* d_in, const int* in_sizes, int n_in,
                              void* d_out, int out_size)
{
    const float* x = (const float*)d_in[0];   // (1,64,32,64,64)
    const float* z = (const float*)d_in[1];   // (1,64,68,132,132)
    const float* W = (const float*)d_in[2];   // (64,64)
    const float* b = (const float*)d_in[3];   // (64,)
    float* out = (float*)d_out;               // (1,128,64,128,128)

    upconv_cropcat_kernel<<<NUM_BLOCKS, 256>>>(x, z, W, b, out);
}